// round 2
// baseline (speedup 1.0000x reference)
#include <cuda_runtime.h>

#define THR  0.05f
#define BETA 0.9181805491303656f
#define TSTEPS 25
#define BATCH  64

// ---------------- persistent state (module device memory; no allocations) ----
#define N1 (BATCH*16*16*128)   // 2,097,152
#define N2 (BATCH*32*8*64)     // 1,048,576
#define N3 (BATCH*64*4*32)     //   524,288

__device__ float g_syn1[N1];
__device__ float g_mem1[2][N1];
__device__ float g_spk1[BATCH*16*8*64];
__device__ float g_syn2[N2];
__device__ float g_mem2[2][N2];
__device__ float g_spk2[BATCH*32*4*32];
__device__ float g_syn3[N3];
__device__ float g_mem3[2][N3];
__device__ float g_spk3[BATCH*64*2*16];
__device__ float g_mem4[BATCH*512];
__device__ float g_spk4[BATCH*512];
__device__ float g_mem5[BATCH*2];

// ---------------- accurate activations (match XLA lowering) -----------------
// XLA expands logistic(x) = 0.5 + 0.5*tanh(0.5*x); tanhf is ~2 ulp accurate.
__device__ __forceinline__ float sigf(float x) {
    return 0.5f + 0.5f * tanhf(0.5f * x);
}
__device__ __forceinline__ float tanh_acc(float x) {
    return tanhf(x);
}

// ---------------- fused SConvLSTM layer -------------------------------------
// One block = (batch b, pooled row ph). Thread (pw, c0) computes hidden
// channels {c0, c0+CH/2} for the 2x2 raw cell under pooled (ph, pw):
// conv gates -> syn/mem update -> maxpool -> threshold spike. Fully fused.
template<int CIN, int CH, int H, int W>
__global__ void __launch_bounds__(512)
sconvlstm_kernel(const float* __restrict__ xin,    // (B,CIN,H,W)
                 const float* __restrict__ memin,  // (B,CH,H,W)  prev mem
                 float*       __restrict__ syn,    // (B,CH,H,W)  in-place
                 float*       __restrict__ memout, // (B,CH,H,W)  next mem
                 float*       __restrict__ spk,    // (B,CH,H/2,W/2)
                 const float* __restrict__ wgt,    // (4CH, CIN+CH, 3, 3)
                 const float* __restrict__ bias)   // (4CH)
{
    constexpr int CT  = CIN + CH;
    constexpr int PH  = H / 2, PW = W / 2;
    constexpr int WP  = W + 2;
    constexpr int CHH = CH / 2;
    constexpr int NT  = PW * CHH;
    extern __shared__ float s_in[];                // [CT][4][WP]

    const int ph = blockIdx.x % PH;
    const int b  = blockIdx.x / PH;
    const int r0 = 2 * ph;
    const int tid = threadIdx.y * PW + threadIdx.x;

    // ---- stage input tile (x ‖ mem), 4 rows (halo), zero-padded cols -------
    constexpr int TILE = CT * 4 * WP;
    for (int i = tid; i < TILE; i += NT) {
        int ch  = i / (4 * WP);
        int rem = i - ch * (4 * WP);
        int rr  = rem / WP;
        int cc  = rem - rr * WP;
        int r = r0 - 1 + rr;
        int c = cc - 1;
        float v = 0.f;
        if ((unsigned)r < (unsigned)H && (unsigned)c < (unsigned)W) {
            v = (ch < CIN) ? xin  [((b * CIN + ch)        * H + r) * W + c]
                           : memin[((b * CH  + (ch - CIN)) * H + r) * W + c];
        }
        s_in[i] = v;
    }
    __syncthreads();

    const int pw = threadIdx.x;
    const int c0 = threadIdx.y;
    const int w0 = 2 * pw;

    float acc[2][4][4];
    #pragma unroll
    for (int u = 0; u < 2; u++) {
        int c = c0 + u * CHH;
        #pragma unroll
        for (int g = 0; g < 4; g++) {
            float bv = __ldg(bias + g * CH + c);
            #pragma unroll
            for (int p = 0; p < 4; p++) acc[u][g][p] = bv;
        }
    }

    for (int ic = 0; ic < CT; ic++) {
        const float* sp = s_in + ic * (4 * WP) + w0;   // 8-byte aligned (w0 even)
        float patch[4][4];
        #pragma unroll
        for (int rr = 0; rr < 4; rr++) {
            float2 a = *reinterpret_cast<const float2*>(sp + rr * WP);
            float2 d = *reinterpret_cast<const float2*>(sp + rr * WP + 2);
            patch[rr][0] = a.x; patch[rr][1] = a.y;
            patch[rr][2] = d.x; patch[rr][3] = d.y;
        }
        #pragma unroll
        for (int u = 0; u < 2; u++) {
            const int c = c0 + u * CHH;
            #pragma unroll
            for (int g = 0; g < 4; g++) {
                const float* wr = wgt + ((size_t)(g * CH + c) * CT + ic) * 9;
                #pragma unroll
                for (int kh = 0; kh < 3; kh++) {
                    #pragma unroll
                    for (int kw = 0; kw < 3; kw++) {
                        float wv = __ldg(wr + kh * 3 + kw);   // warp-uniform
                        acc[u][g][0] = fmaf(wv, patch[kh    ][kw    ], acc[u][g][0]);
                        acc[u][g][1] = fmaf(wv, patch[kh    ][kw + 1], acc[u][g][1]);
                        acc[u][g][2] = fmaf(wv, patch[kh + 1][kw    ], acc[u][g][2]);
                        acc[u][g][3] = fmaf(wv, patch[kh + 1][kw + 1], acc[u][g][3]);
                    }
                }
            }
        }
    }

    // ---- gate math + recurrence + maxpool + spike ---------------------------
    #pragma unroll
    for (int u = 0; u < 2; u++) {
        const int c = c0 + u * CHH;
        float mx = -1e30f;
        #pragma unroll
        for (int pr = 0; pr < 2; pr++) {
            #pragma unroll
            for (int pc = 0; pc < 2; pc++) {
                const int p = pr * 2 + pc;
                float gi = sigf(acc[u][0][p]);
                float gf = sigf(acc[u][1][p]);
                float gg = tanh_acc(acc[u][2][p]);
                float go = sigf(acc[u][3][p]);
                int idx = ((b * CH + c) * H + (r0 + pr)) * W + (w0 + pc);
                float sv = gf * syn[idx] + gi * gg;
                syn[idx] = sv;
                float m = go * tanh_acc(sv);
                memout[idx] = m;
                mx = fmaxf(mx, m);
            }
        }
        spk[((b * CH + c) * PH + ph) * PW + pw] = (mx > THR) ? 1.f : 0.f;
    }
}

// ---------------- FC1 (64x512x2048 GEMM) + Leaky, fused epilogue ------------
__global__ void __launch_bounds__(256)
fc1_leaky_kernel(const float* __restrict__ spk3,  // (64, 2048)
                 const float* __restrict__ w,     // (512, 2048)
                 const float* __restrict__ bias,  // (512)
                 float*       __restrict__ mem4,  // (64, 512) in-place
                 float*       __restrict__ spk4)  // (64, 512)
{
    __shared__ float As[64][33];
    __shared__ float Bs[64][33];
    const int tid   = threadIdx.x;
    const int nbase = blockIdx.x * 64;
    const int m0 = (tid / 16) * 4;
    const int n0 = (tid % 16) * 4;
    float acc[4][4] = {};

    for (int kk = 0; kk < 2048; kk += 32) {
        for (int e = tid; e < 2048; e += 256) {
            int row = e >> 5, k = e & 31;
            As[row][k] = spk3[row * 2048 + kk + k];
            Bs[row][k] = w[(size_t)(nbase + row) * 2048 + kk + k];
        }
        __syncthreads();
        #pragma unroll
        for (int k = 0; k < 32; k++) {
            float a[4], d[4];
            #pragma unroll
            for (int i = 0; i < 4; i++) a[i] = As[m0 + i][k];
            #pragma unroll
            for (int j = 0; j < 4; j++) d[j] = Bs[n0 + j][k];
            #pragma unroll
            for (int i = 0; i < 4; i++)
                #pragma unroll
                for (int j = 0; j < 4; j++)
                    acc[i][j] = fmaf(a[i], d[j], acc[i][j]);
        }
        __syncthreads();
    }

    #pragma unroll
    for (int i = 0; i < 4; i++) {
        #pragma unroll
        for (int j = 0; j < 4; j++) {
            int bidx = m0 + i;
            int n = nbase + n0 + j;
            float cur = acc[i][j] + bias[n];
            int idx = bidx * 512 + n;
            float mo = mem4[idx];
            float reset = (mo > THR) ? THR : 0.f;       // reset from PREVIOUS mem
            float mn = BETA * mo + cur - reset;
            mem4[idx] = mn;
            spk4[idx] = ((mn - THR) > 0.f) ? 1.f : 0.f;
        }
    }
}

// ---------------- FC2 + Leaky + output write --------------------------------
__global__ void fc2_leaky_out_kernel(const float* __restrict__ spk4,  // (64,512)
                                     const float* __restrict__ w,     // (2,512)
                                     const float* __restrict__ bias,  // (2)
                                     float*       __restrict__ mem5,  // (64,2)
                                     float*       __restrict__ out,   // [spk(25,64,2); mem(25,64,2)]
                                     int t)
{
    int tid = threadIdx.x;           // 128 threads = 64 b x 2 o
    int b = tid >> 1, o = tid & 1;
    const float* sr = spk4 + b * 512;
    const float* wr = w + o * 512;
    float acc = bias[o];
    #pragma unroll 8
    for (int k = 0; k < 512; k++) acc = fmaf(sr[k], wr[k], acc);
    float mo = mem5[tid];
    float reset = (mo > THR) ? THR : 0.f;
    float mn = BETA * mo + acc - reset;
    mem5[tid] = mn;
    int oidx = (t * BATCH + b) * 2 + o;
    out[oidx] = ((mn - THR) > 0.f) ? 1.f : 0.f;        // spk_rec
    out[TSTEPS * BATCH * 2 + oidx] = mn;               // mem_rec
}

// ---------------- state zero-init (carry = zeros every call) ----------------
__global__ void zero_state_kernel() {
    int i = blockIdx.x * blockDim.x + threadIdx.x;
    int stride = gridDim.x * blockDim.x;
    for (int j = i; j < N1; j += stride) { g_syn1[j] = 0.f; g_mem1[0][j] = 0.f; }
    for (int j = i; j < N2; j += stride) { g_syn2[j] = 0.f; g_mem2[0][j] = 0.f; }
    for (int j = i; j < N3; j += stride) { g_syn3[j] = 0.f; g_mem3[0][j] = 0.f; }
    for (int j = i; j < BATCH * 512; j += stride) g_mem4[j] = 0.f;
    for (int j = i; j < BATCH * 2;   j += stride) g_mem5[j] = 0.f;
}

// ---------------- host launcher ---------------------------------------------
extern "C" void kernel_launch(void* const* d_in, const int* in_sizes, int n_in,
                              void* d_out, int out_size) {
    const float* x    = (const float*)d_in[0];
    const float* w1   = (const float*)d_in[1];
    const float* b1   = (const float*)d_in[2];
    const float* w2   = (const float*)d_in[3];
    const float* b2   = (const float*)d_in[4];
    const float* w3   = (const float*)d_in[5];
    const float* b3   = (const float*)d_in[6];
    const float* fc1w = (const float*)d_in[7];
    const float* fc1b = (const float*)d_in[8];
    const float* fc2w = (const float*)d_in[9];
    const float* fc2b = (const float*)d_in[10];
    float* out = (float*)d_out;

    float *p_syn1, *p_mem1, *p_spk1;
    float *p_syn2, *p_mem2, *p_spk2;
    float *p_syn3, *p_mem3, *p_spk3;
    float *p_mem4, *p_spk4, *p_mem5;
    cudaGetSymbolAddress((void**)&p_syn1, g_syn1);
    cudaGetSymbolAddress((void**)&p_mem1, g_mem1);
    cudaGetSymbolAddress((void**)&p_spk1, g_spk1);
    cudaGetSymbolAddress((void**)&p_syn2, g_syn2);
    cudaGetSymbolAddress((void**)&p_mem2, g_mem2);
    cudaGetSymbolAddress((void**)&p_spk2, g_spk2);
    cudaGetSymbolAddress((void**)&p_syn3, g_syn3);
    cudaGetSymbolAddress((void**)&p_mem3, g_mem3);
    cudaGetSymbolAddress((void**)&p_spk3, g_spk3);
    cudaGetSymbolAddress((void**)&p_mem4, g_mem4);
    cudaGetSymbolAddress((void**)&p_spk4, g_spk4);
    cudaGetSymbolAddress((void**)&p_mem5, g_mem5);

    constexpr int SM1 = 17 * 4 * 130 * 4;  // 35,360 B
    constexpr int SM2 = 48 * 4 * 66  * 4;  // 50,688 B
    constexpr int SM3 = 96 * 4 * 34  * 4;  // 52,224 B
    cudaFuncSetAttribute(sconvlstm_kernel<1, 16, 16, 128>,
                         cudaFuncAttributeMaxDynamicSharedMemorySize, SM1);
    cudaFuncSetAttribute(sconvlstm_kernel<16, 32, 8, 64>,
                         cudaFuncAttributeMaxDynamicSharedMemorySize, SM2);
    cudaFuncSetAttribute(sconvlstm_kernel<32, 64, 4, 32>,
                         cudaFuncAttributeMaxDynamicSharedMemorySize, SM3);

    zero_state_kernel<<<512, 256>>>();

    for (int t = 0; t < TSTEPS; t++) {
        int p = t & 1;
        sconvlstm_kernel<1, 16, 16, 128><<<BATCH * 8, dim3(64, 8), SM1>>>(
            x + (size_t)t * BATCH * 16 * 128,
            p_mem1 + p * N1, p_syn1, p_mem1 + (1 - p) * N1, p_spk1, w1, b1);
        sconvlstm_kernel<16, 32, 8, 64><<<BATCH * 4, dim3(32, 16), SM2>>>(
            p_spk1, p_mem2 + p * N2, p_syn2, p_mem2 + (1 - p) * N2, p_spk2, w2, b2);
        sconvlstm_kernel<32, 64, 4, 32><<<BATCH * 2, dim3(16, 32), SM3>>>(
            p_spk2, p_mem3 + p * N3, p_syn3, p_mem3 + (1 - p) * N3, p_spk3, w3, b3);
        fc1_leaky_kernel<<<8, 256>>>(p_spk3, fc1w, fc1b, p_mem4, p_spk4);
        fc2_leaky_out_kernel<<<1, 128>>>(p_spk4, fc2w, fc2b, p_mem5, out, t);
    }
}